// round 2
// baseline (speedup 1.0000x reference)
#include <cuda_runtime.h>
#include <math_constants.h>

#define B_ROWS   131072
#define D_EMB    256
#define K_CODES  512
#define QSIZE    128
#define TM       128
#define TN       128
#define TK       16
#define TILES_M  (B_ROWS / TM)      // 1024
#define NPART    (TILES_M * 4)      // 4096

// ---- device scratch (static; no allocations allowed) ----
__device__ int   g_counts[4];
__device__ int   g_buckets[4 * B_ROWS];     // 2 MB
__device__ float g_enorm[K_CODES];
__device__ float g_znorm[B_ROWS];
__device__ float g_partial[NPART];

// ---------------------------------------------------------------------------
__global__ void reset_kernel() {
    if (threadIdx.x < 4) g_counts[threadIdx.x] = 0;
}

__global__ void classify_kernel(const int* __restrict__ node_type) {
    int i = blockIdx.x * blockDim.x + threadIdx.x;
    int t = node_type[i];
    int g = (t == 5) ? 0 : (t == 6) ? 1 : (t == 7) ? 2 : 3;
    int pos = atomicAdd(&g_counts[g], 1);
    g_buckets[g * B_ROWS + pos] = i;
}

__global__ void enorm_kernel(const float* __restrict__ cb) {
    int c = blockIdx.x * blockDim.x + threadIdx.x;
    if (c < K_CODES) {
        const float* row = cb + (size_t)c * D_EMB;
        float s = 0.f;
        #pragma unroll 8
        for (int k = 0; k < D_EMB; ++k) s = fmaf(row[k], row[k], s);
        g_enorm[c] = s;
    }
}

__global__ void znorm_kernel(const float* __restrict__ z) {
    int row  = blockIdx.x * (blockDim.x / 32) + (threadIdx.x >> 5);
    int lane = threadIdx.x & 31;
    const float* zr = z + (size_t)row * D_EMB;
    float s = 0.f;
    #pragma unroll
    for (int k = lane; k < D_EMB; k += 32) s = fmaf(zr[k], zr[k], s);
    #pragma unroll
    for (int o = 16; o; o >>= 1) s += __shfl_xor_sync(0xffffffffu, s, o);
    if (lane == 0) g_znorm[row] = s;
}

// ---------------------------------------------------------------------------
// One block: 128 gathered rows (one quadrant) x 128 codes x K=256.
// 256 threads, 8x8 micro-tiles (strided: row = ty+16*i, code = tx+16*j).
__global__ void __launch_bounds__(256) vq_gemm_kernel(
    const float* __restrict__ z, const float* __restrict__ cb,
    float* __restrict__ out)
{
    __shared__ float zs[TK][TM + 1];
    __shared__ float es[TK][TN + 1];
    __shared__ int   s_rows[TM];
    __shared__ float s_zn[TM];
    __shared__ float s_en[TN];
    __shared__ float s_minval[TM][16];
    __shared__ int   s_minidx[TM][16];
    __shared__ int   s_sel[TM];
    __shared__ float s_red[256];

    const int g     = blockIdx.y;
    const int cnt   = g_counts[g];
    const int start = blockIdx.x * TM;
    const int pid   = g * TILES_M + blockIdx.x;
    const int tid   = threadIdx.x;

    if (start >= cnt) {                 // empty tile: still publish a partial
        if (tid == 0) g_partial[pid] = 0.f;
        return;
    }

    if (tid < TM) {
        int r = (start + tid < cnt) ? g_buckets[g * B_ROWS + start + tid] : -1;
        s_rows[tid] = r;
        s_zn[tid]   = (r >= 0) ? g_znorm[r] : 0.f;
        s_en[tid]   = g_enorm[g * QSIZE + tid];
    }
    __syncthreads();

    float acc[8][8];
    #pragma unroll
    for (int i = 0; i < 8; ++i)
        #pragma unroll
        for (int j = 0; j < 8; ++j) acc[i][j] = 0.f;

    const int lm = tid >> 1;      // 0..127 : row slot / code slot for loading
    const int lh = tid & 1;       // which 8-float half of the 16-wide k tile
    const int row_g = s_rows[lm];
    const int ty = tid >> 4;      // 0..15
    const int tx = tid & 15;      // 0..15

    for (int kt = 0; kt < D_EMB; kt += TK) {
        float4 a0, a1;
        if (row_g >= 0) {
            const float* p = z + (size_t)row_g * D_EMB + kt + lh * 8;
            a0 = *(const float4*)p;  a1 = *(const float4*)(p + 4);
        } else {
            a0 = make_float4(0.f, 0.f, 0.f, 0.f);  a1 = a0;
        }
        const float* q = cb + (size_t)(g * QSIZE + lm) * D_EMB + kt + lh * 8;
        float4 b0 = *(const float4*)q;  float4 b1 = *(const float4*)(q + 4);

        __syncthreads();   // previous tile's compute done
        zs[lh*8+0][lm] = a0.x;  zs[lh*8+1][lm] = a0.y;
        zs[lh*8+2][lm] = a0.z;  zs[lh*8+3][lm] = a0.w;
        zs[lh*8+4][lm] = a1.x;  zs[lh*8+5][lm] = a1.y;
        zs[lh*8+6][lm] = a1.z;  zs[lh*8+7][lm] = a1.w;
        es[lh*8+0][lm] = b0.x;  es[lh*8+1][lm] = b0.y;
        es[lh*8+2][lm] = b0.z;  es[lh*8+3][lm] = b0.w;
        es[lh*8+4][lm] = b1.x;  es[lh*8+5][lm] = b1.y;
        es[lh*8+6][lm] = b1.z;  es[lh*8+7][lm] = b1.w;
        __syncthreads();

        #pragma unroll
        for (int k = 0; k < TK; ++k) {
            float zr[8], er[8];
            #pragma unroll
            for (int i = 0; i < 8; ++i) zr[i] = zs[k][ty + 16 * i];
            #pragma unroll
            for (int j = 0; j < 8; ++j) er[j] = es[k][tx + 16 * j];
            #pragma unroll
            for (int i = 0; i < 8; ++i)
                #pragma unroll
                for (int j = 0; j < 8; ++j)
                    acc[i][j] = fmaf(zr[i], er[j], acc[i][j]);
        }
    }

    // ---- argmin: score = (||z||^2 + ||e||^2) - 2*dot  (ref association) ----
    #pragma unroll
    for (int i = 0; i < 8; ++i) {
        int row  = ty + 16 * i;
        float zn = s_zn[row];
        float best = CUDART_INF_F;  int bi = 0x7fffffff;
        #pragma unroll
        for (int j = 0; j < 8; ++j) {
            int code = tx + 16 * j;
            float s = (zn + s_en[code]) - 2.0f * acc[i][j];
            if (s < best || (s == best && code < bi)) { best = s; bi = code; }
        }
        s_minval[row][tx] = best;
        s_minidx[row][tx] = bi;
    }
    __syncthreads();

    if (tid < TM) {
        float best = s_minval[tid][0];  int bi = s_minidx[tid][0];
        #pragma unroll
        for (int t = 1; t < 16; ++t) {
            float v = s_minval[tid][t];  int ix = s_minidx[tid][t];
            if (v < best || (v == best && ix < bi)) { best = v; bi = ix; }
        }
        s_sel[tid] = bi;
        int r = s_rows[tid];
        if (r >= 0) out[2 + r] = (float)(g * QSIZE + bi);   // idx output
    }
    __syncthreads();

    // ---- epilogue: st = z + (q - z), loss partial (deterministic) ----
    // NOTE: the st region starts at float offset 2 + B_ROWS (8-byte aligned
    // only), so stores use float2; loads from z/cb stay float4 (16B-aligned).
    float sumsq = 0.f;
    {
        int m = tid >> 1;  int half = tid & 1;
        int r = s_rows[m];
        if (r >= 0) {
            int code = g * QSIZE + s_sel[m];
            const float* zr = z  + (size_t)r    * D_EMB + half * 128;
            const float* qr = cb + (size_t)code * D_EMB + half * 128;
            float* so = out + 2 + B_ROWS + (size_t)r * D_EMB + half * 128;
            #pragma unroll 4
            for (int c = 0; c < 128; c += 4) {
                float4 zv = *(const float4*)(zr + c);
                float4 qv = *(const float4*)(qr + c);
                float dx = qv.x - zv.x, dy = qv.y - zv.y;
                float dz = qv.z - zv.z, dw = qv.w - zv.w;
                float2 s0 = make_float2(zv.x + dx, zv.y + dy);
                float2 s1 = make_float2(zv.z + dz, zv.w + dw);
                *(float2*)(so + c)     = s0;
                *(float2*)(so + c + 2) = s1;
                sumsq += dx*dx;  sumsq += dy*dy;  sumsq += dz*dz;  sumsq += dw*dw;
            }
        }
    }
    s_red[tid] = sumsq;
    __syncthreads();
    #pragma unroll
    for (int o = 128; o; o >>= 1) {
        if (tid < o) s_red[tid] += s_red[tid + o];
        __syncthreads();
    }
    if (tid == 0) g_partial[pid] = s_red[0];
}

// ---------------------------------------------------------------------------
__global__ void finalize_kernel(float* __restrict__ out) {
    __shared__ double sd[256];
    double s = 0.0;
    for (int i = threadIdx.x; i < NPART; i += 256) s += (double)g_partial[i];
    sd[threadIdx.x] = s;
    __syncthreads();
    #pragma unroll
    for (int o = 128; o; o >>= 1) {
        if (threadIdx.x < o) sd[threadIdx.x] += sd[threadIdx.x + o];
        __syncthreads();
    }
    if (threadIdx.x == 0) {
        float vq = (float)(sd[0] / ((double)B_ROWS * (double)D_EMB));
        out[0] = vq;            // vq_loss
        out[1] = 0.25f * vq;    // commitment = COST * same mean
    }
}

// ---------------------------------------------------------------------------
extern "C" void kernel_launch(void* const* d_in, const int* in_sizes, int n_in,
                              void* d_out, int out_size) {
    const int*   node_type = (const int*)d_in[0];
    const float* z         = (const float*)d_in[1];
    const float* cb        = (const float*)d_in[2];
    float* out = (float*)d_out;

    reset_kernel<<<1, 32>>>();
    classify_kernel<<<B_ROWS / 256, 256>>>(node_type);
    enorm_kernel<<<2, 256>>>(cb);
    znorm_kernel<<<B_ROWS / 8, 256>>>(z);
    dim3 grid(TILES_M, 4);
    vq_gemm_kernel<<<grid, 256>>>(z, cb, out);
    finalize_kernel<<<1, 256>>>(out);
}

// round 4
// speedup vs baseline: 1.3603x; 1.3603x over previous
#include <cuda_runtime.h>
#include <cuda_bf16.h>
#include <math_constants.h>

#define B_ROWS   131072
#define D_EMB    256
#define QSIZE    128
#define TM       128
#define TILES_M  (B_ROWS / TM)   // 1024
#define MARGIN   0.02f

// ---------------- device scratch (static) ----------------
__device__ int    g_counts[4];
__device__ int    g_buckets[4 * B_ROWS];
__device__ float  g_rowloss[B_ROWS];
__device__ double g_bsum[256];

// ---------------- small kernels ----------------
__global__ void reset_kernel() {
    if (threadIdx.x < 4) g_counts[threadIdx.x] = 0;
}
__global__ void classify_kernel(const int* __restrict__ node_type) {
    int i = blockIdx.x * blockDim.x + threadIdx.x;
    int t = node_type[i];
    int g = (t == 5) ? 0 : (t == 6) ? 1 : (t == 7) ? 2 : 3;
    int pos = atomicAdd(&g_counts[g], 1);
    g_buckets[g * B_ROWS + pos] = i;
}

// ---------------- smem layout (dynamic) ----------------
// bf16 tiles: 128 rows x 72 bf16 (k-chunk of 64 + 8 pad) = 144 B/row
#define ROWB     144
#define T_BYTES  (128 * ROWB)          // 18432
#define OFF_ABIG 0
#define OFF_ASML (OFF_ABIG + T_BYTES)
#define OFF_BBIG (OFF_ASML + T_BYTES)
#define OFF_BSML (OFF_BBIG + T_BYTES)
#define OFF_ROWS (OFF_BSML + T_BYTES)              // 128 int
#define OFF_ZNP  (OFF_ROWS + 512)                  // 256 float
#define OFF_ENP  (OFF_ZNP + 1024)                  // 256 float
#define OFF_ZN   (OFF_ENP + 1024)                  // 128 float
#define OFF_EN   (OFF_ZN + 512)                    // 128 float
#define OFF_SEL  (OFF_EN + 512)                    // 128 int
#define OFF_NC   (OFF_SEL + 512)                   // 128 int
#define OFF_CAND (OFF_NC + 512)                    // 128*8 int
#define OFF_LOSS (OFF_CAND + 4096)                 // 256 float
#define SMEM_DYN (OFF_LOSS + 1024)

__device__ __forceinline__ void mma_bf16(float* d, const unsigned* a,
                                         const unsigned* b) {
    asm volatile(
        "mma.sync.aligned.m16n8k16.row.col.f32.bf16.bf16.f32 "
        "{%0,%1,%2,%3}, {%4,%5,%6,%7}, {%8,%9}, {%0,%1,%2,%3};"
        : "+f"(d[0]), "+f"(d[1]), "+f"(d[2]), "+f"(d[3])
        : "r"(a[0]), "r"(a[1]), "r"(a[2]), "r"(a[3]), "r"(b[0]), "r"(b[1]));
}

__device__ __forceinline__ unsigned pack_big(float x, float y, float& rx, float& ry) {
    __nv_bfloat16 bx = __float2bfloat16(x), by = __float2bfloat16(y);
    rx = x - __bfloat162float(bx);
    ry = y - __bfloat162float(by);
    __nv_bfloat162 p; p.x = bx; p.y = by;
    return *(unsigned*)&p;
}
__device__ __forceinline__ unsigned pack_sml(float x, float y) {
    __nv_bfloat162 p; p.x = __float2bfloat16(x); p.y = __float2bfloat16(y);
    return *(unsigned*)&p;
}

// ---------------- main kernel ----------------
__global__ void __launch_bounds__(256, 2) vq_mma_kernel(
    const float* __restrict__ z, const float* __restrict__ cb,
    float* __restrict__ out)
{
    extern __shared__ char sm[];
    const int g   = blockIdx.y;
    const int tid = threadIdx.x;
    const int cnt   = g_counts[g];
    const int start = blockIdx.x * TM;
    if (start >= cnt) return;

    int*   s_rows = (int*)  (sm + OFF_ROWS);
    float* s_znp  = (float*)(sm + OFF_ZNP);
    float* s_enp  = (float*)(sm + OFF_ENP);
    float* s_zn   = (float*)(sm + OFF_ZN);
    float* s_en   = (float*)(sm + OFF_EN);
    int*   s_sel  = (int*)  (sm + OFF_SEL);
    int*   s_nc   = (int*)  (sm + OFF_NC);
    int*   s_cand = (int*)  (sm + OFF_CAND);
    float* s_loss = (float*)(sm + OFF_LOSS);

    if (tid < TM) {
        int r = (start + tid < cnt) ? g_buckets[g * B_ROWS + start + tid] : -1;
        s_rows[tid] = r;
        s_nc[tid] = 0;
    }
    __syncthreads();

    // loader mapping: thread = 2*row + h, each handles 32 floats per chunk
    const int lrow = tid >> 1, lh = tid & 1;
    const int gr = s_rows[lrow];
    const float* zrow = z  + (size_t)(gr < 0 ? 0 : gr) * D_EMB;
    const float* erow = cb + (size_t)(g * QSIZE + lrow) * D_EMB;

    // mma mapping
    const int w = tid >> 5, lane = tid & 31;
    const int gq = lane >> 2, t = lane & 3;
    const int R0 = w * 16;

    float acc[16][4];
    #pragma unroll
    for (int nf = 0; nf < 16; ++nf)
        #pragma unroll
        for (int q = 0; q < 4; ++q) acc[nf][q] = 0.f;

    float zn_acc = 0.f, en_acc = 0.f;

    #pragma unroll 1
    for (int c = 0; c < 4; ++c) {
        const int kbase = c * 64 + lh * 32;
        float4 zv[8], ev[8];
        #pragma unroll
        for (int j = 0; j < 8; ++j) zv[j] = *(const float4*)(zrow + kbase + 4 * j);
        #pragma unroll
        for (int j = 0; j < 8; ++j) ev[j] = *(const float4*)(erow + kbase + 4 * j);

        __syncthreads();   // previous chunk's mma done before overwrite

        #pragma unroll
        for (int j = 0; j < 8; ++j) {
            float4 v = zv[j];
            zn_acc += v.x * v.x; zn_acc += v.y * v.y;
            zn_acc += v.z * v.z; zn_acc += v.w * v.w;
            float sx, sy, sz, sw;
            unsigned b0 = pack_big(v.x, v.y, sx, sy);
            unsigned b1 = pack_big(v.z, v.w, sz, sw);
            unsigned s0 = pack_sml(sx, sy);
            unsigned s1 = pack_sml(sz, sw);
            unsigned off = lrow * ROWB + (lh * 32 + 4 * j) * 2;
            *(uint2*)(sm + OFF_ABIG + off) = make_uint2(b0, b1);
            *(uint2*)(sm + OFF_ASML + off) = make_uint2(s0, s1);

            float4 e = ev[j];
            en_acc += e.x * e.x; en_acc += e.y * e.y;
            en_acc += e.z * e.z; en_acc += e.w * e.w;
            unsigned eb0 = pack_big(e.x, e.y, sx, sy);
            unsigned eb1 = pack_big(e.z, e.w, sz, sw);
            unsigned es0 = pack_sml(sx, sy);
            unsigned es1 = pack_sml(sz, sw);
            *(uint2*)(sm + OFF_BBIG + off) = make_uint2(eb0, eb1);
            *(uint2*)(sm + OFF_BSML + off) = make_uint2(es0, es1);
        }
        __syncthreads();

        #pragma unroll
        for (int kk = 0; kk < 4; ++kk) {
            const unsigned abase = (R0 + gq) * ROWB + kk * 32 + t * 4;
            unsigned ab[4], as[4];
            ab[0] = *(const unsigned*)(sm + OFF_ABIG + abase);
            ab[1] = *(const unsigned*)(sm + OFF_ABIG + abase + 8 * ROWB);
            ab[2] = *(const unsigned*)(sm + OFF_ABIG + abase + 16);
            ab[3] = *(const unsigned*)(sm + OFF_ABIG + abase + 8 * ROWB + 16);
            as[0] = *(const unsigned*)(sm + OFF_ASML + abase);
            as[1] = *(const unsigned*)(sm + OFF_ASML + abase + 8 * ROWB);
            as[2] = *(const unsigned*)(sm + OFF_ASML + abase + 16);
            as[3] = *(const unsigned*)(sm + OFF_ASML + abase + 8 * ROWB + 16);
            #pragma unroll
            for (int nf = 0; nf < 16; ++nf) {
                const unsigned bbase = (nf * 8 + gq) * ROWB + kk * 32 + t * 4;
                unsigned bb[2], bs[2];
                bb[0] = *(const unsigned*)(sm + OFF_BBIG + bbase);
                bb[1] = *(const unsigned*)(sm + OFF_BBIG + bbase + 16);
                bs[0] = *(const unsigned*)(sm + OFF_BSML + bbase);
                bs[1] = *(const unsigned*)(sm + OFF_BSML + bbase + 16);
                mma_bf16(acc[nf], ab, bb);
                mma_bf16(acc[nf], ab, bs);
                mma_bf16(acc[nf], as, bb);
            }
        }
    }

    s_znp[tid] = zn_acc;
    s_enp[tid] = en_acc;
    __syncthreads();
    if (tid < TM) {
        s_zn[tid] = s_znp[2 * tid] + s_znp[2 * tid + 1];
        s_en[tid] = s_enp[2 * tid] + s_enp[2 * tid + 1];
    }
    __syncthreads();

    // ---- approx argmin per row (two rows per thread) ----
    const int rowA = R0 + gq, rowB = R0 + gq + 8;
    const float znA = s_zn[rowA], znB = s_zn[rowB];
    float vA = CUDART_INF_F, vB = CUDART_INF_F;
    int cA = 0x7fffffff, cB = 0x7fffffff;
    #pragma unroll
    for (int nf = 0; nf < 16; ++nf) {
        #pragma unroll
        for (int q = 0; q < 2; ++q) {
            int col = nf * 8 + 2 * t + q;
            float en = s_en[col];
            float sa = fmaf(-2.f, acc[nf][q],     znA + en);
            float sb = fmaf(-2.f, acc[nf][q + 2], znB + en);
            if (sa < vA || (sa == vA && col < cA)) { vA = sa; cA = col; }
            if (sb < vB || (sb == vB && col < cB)) { vB = sb; cB = col; }
        }
    }
    #pragma unroll
    for (int off = 1; off < 4; off <<= 1) {
        float v2 = __shfl_xor_sync(0xffffffffu, vA, off);
        int   c2 = __shfl_xor_sync(0xffffffffu, cA, off);
        if (v2 < vA || (v2 == vA && c2 < cA)) { vA = v2; cA = c2; }
        v2 = __shfl_xor_sync(0xffffffffu, vB, off);
        c2 = __shfl_xor_sync(0xffffffffu, cB, off);
        if (v2 < vB || (v2 == vB && c2 < cB)) { vB = v2; cB = c2; }
    }
    if (t == 0) { s_sel[rowA] = cA; s_sel[rowB] = cB; }

    // ---- candidate collection within MARGIN of approx min ----
    #pragma unroll
    for (int nf = 0; nf < 16; ++nf) {
        #pragma unroll
        for (int q = 0; q < 2; ++q) {
            int col = nf * 8 + 2 * t + q;
            float en = s_en[col];
            float sa = fmaf(-2.f, acc[nf][q],     znA + en);
            float sb = fmaf(-2.f, acc[nf][q + 2], znB + en);
            if (sa <= vA + MARGIN) {
                int p = atomicAdd(&s_nc[rowA], 1);
                if (p < 8) s_cand[rowA * 8 + p] = col;
            }
            if (sb <= vB + MARGIN) {
                int p = atomicAdd(&s_nc[rowB], 1);
                if (p < 8) s_cand[rowB * 8 + p] = col;
            }
        }
    }
    __syncthreads();

    // ---- exact fp32 rescue for ambiguous rows (warp per row-slice) ----
    for (int m = R0; m < R0 + 16; ++m) {
        int nc = s_nc[m];
        int r  = s_rows[m];
        if (r < 0 || nc <= 1) continue;
        const float* zr = z + (size_t)r * D_EMB;
        float zn = s_zn[m];
        float bestv = CUDART_INF_F;  int bestc = 0x7fffffff;
        int nit = (nc <= 8) ? nc : QSIZE;
        for (int i = 0; i < nit; ++i) {
            int col = (nc <= 8) ? s_cand[m * 8 + i] : i;
            const float* er = cb + (size_t)(g * QSIZE + col) * D_EMB;
            float p = 0.f;
            #pragma unroll
            for (int j = 0; j < 8; ++j)
                p = fmaf(zr[lane + 32 * j], er[lane + 32 * j], p);
            #pragma unroll
            for (int off = 16; off; off >>= 1)
                p += __shfl_xor_sync(0xffffffffu, p, off);
            float sc = fmaf(-2.f, p, zn + s_en[col]);
            if (sc < bestv || (sc == bestv && col < bestc)) { bestv = sc; bestc = col; }
        }
        if (lane == 0) s_sel[m] = bestc;
    }
    __syncthreads();

    if (tid < TM) {
        int r = s_rows[tid];
        if (r >= 0) out[2 + r] = (float)(g * QSIZE + s_sel[tid]);
    }

    // ---- epilogue: st = z + (q - z), per-row loss ----
    {
        int m = tid >> 1, h = tid & 1;
        int r = s_rows[m];
        float lsum = 0.f;
        if (r >= 0) {
            int code = g * QSIZE + s_sel[m];
            const float* zr = z  + (size_t)r    * D_EMB + h * 128;
            const float* qr = cb + (size_t)code * D_EMB + h * 128;
            float* so = out + 2 + B_ROWS + (size_t)r * D_EMB + h * 128;
            #pragma unroll 4
            for (int cc = 0; cc < 128; cc += 4) {
                float4 zv = *(const float4*)(zr + cc);
                float4 qv = *(const float4*)(qr + cc);
                float dx = qv.x - zv.x, dy = qv.y - zv.y;
                float dz = qv.z - zv.z, dw = qv.w - zv.w;
                *(float2*)(so + cc)     = make_float2(zv.x + dx, zv.y + dy);
                *(float2*)(so + cc + 2) = make_float2(zv.z + dz, zv.w + dw);
                lsum += dx * dx; lsum += dy * dy; lsum += dz * dz; lsum += dw * dw;
            }
        }
        s_loss[tid] = lsum;
    }
    __syncthreads();
    if (tid < TM) {
        int r = s_rows[tid];
        if (r >= 0) g_rowloss[r] = s_loss[2 * tid] + s_loss[2 * tid + 1];
    }
}

// ---------------- loss reduction ----------------
__global__ void rowloss_reduce_kernel() {
    __shared__ double sd[256];
    int base = blockIdx.x * 512;
    double s = (double)g_rowloss[base + threadIdx.x]
             + (double)g_rowloss[base + 256 + threadIdx.x];
    sd[threadIdx.x] = s;
    __syncthreads();
    #pragma unroll
    for (int o = 128; o; o >>= 1) {
        if (threadIdx.x < o) sd[threadIdx.x] += sd[threadIdx.x + o];
        __syncthreads();
    }
    if (threadIdx.x == 0) g_bsum[blockIdx.x] = sd[0];
}

__global__ void finalize_kernel(float* __restrict__ out) {
    __shared__ double sd[256];
    sd[threadIdx.x] = g_bsum[threadIdx.x];
    __syncthreads();
    #pragma unroll
    for (int o = 128; o; o >>= 1) {
        if (threadIdx.x < o) sd[threadIdx.x] += sd[threadIdx.x + o];
        __syncthreads();
    }
    if (threadIdx.x == 0) {
        float vq = (float)(sd[0] / ((double)B_ROWS * (double)D_EMB));
        out[0] = vq;
        out[1] = 0.25f * vq;
    }
}

// ---------------- launch ----------------
extern "C" void kernel_launch(void* const* d_in, const int* in_sizes, int n_in,
                              void* d_out, int out_size) {
    const int*   node_type = (const int*)d_in[0];
    const float* z         = (const float*)d_in[1];
    const float* cb        = (const float*)d_in[2];
    float* out = (float*)d_out;

    cudaFuncSetAttribute(vq_mma_kernel,
                         cudaFuncAttributeMaxDynamicSharedMemorySize, SMEM_DYN);

    reset_kernel<<<1, 32>>>();
    classify_kernel<<<B_ROWS / 256, 256>>>(node_type);
    dim3 grid(TILES_M, 4);
    vq_mma_kernel<<<grid, 256, SMEM_DYN>>>(z, cb, out);
    rowloss_reduce_kernel<<<256, 256>>>();
    finalize_kernel<<<1, 256>>>(out);
}

// round 5
// speedup vs baseline: 1.3832x; 1.0169x over previous
#include <cuda_runtime.h>
#include <math_constants.h>

#define B_ROWS   131072
#define D_EMB    256
#define QSIZE    128
#define TM       128
#define TILES_M  (B_ROWS / TM)   // 1024
#define MARGIN   1.0f

// ---------------- device scratch (static) ----------------
__device__ int    g_counts[4];
__device__ int    g_buckets[4 * B_ROWS];
__device__ float  g_rowloss[B_ROWS];
__device__ double g_bsum[256];

// ---------------- small kernels ----------------
__global__ void reset_kernel() {
    if (threadIdx.x < 4) g_counts[threadIdx.x] = 0;
}
__global__ void classify_kernel(const int* __restrict__ node_type) {
    int i = blockIdx.x * blockDim.x + threadIdx.x;
    int t = node_type[i];
    int g = (t == 5) ? 0 : (t == 6) ? 1 : (t == 7) ? 2 : 3;
    int pos = atomicAdd(&g_counts[g], 1);
    g_buckets[g * B_ROWS + pos] = i;
}

// ---------------- smem layout ----------------
// tf32 tiles, row-major, ROWB=68 floats/row (64 data + 4 pad).
// Pad=4 floats => mma fragment LDS banks = gq*4+t : conflict-free.
#define ROWB     68
#define T_FLOATS (128 * ROWB)                       // 8704 floats = 34816 B
#define OFF_A    0
#define OFF_B    (T_FLOATS * 4)                     // 34816
#define OFF_ROWS (2 * T_FLOATS * 4)                 // 69632, 128 int
#define OFF_ZNP  (OFF_ROWS + 512)                   // 256 float
#define OFF_ENP  (OFF_ZNP + 1024)                   // 256 float
#define OFF_ZN   (OFF_ENP + 1024)                   // 128 float
#define OFF_EN   (OFF_ZN + 512)                     // 128 float
#define OFF_SEL  (OFF_EN + 512)                     // 128 int
#define OFF_NC   (OFF_SEL + 512)                    // 128 int
#define OFF_CAND (OFF_NC + 512)                     // 128*8 int
#define OFF_LOSS (OFF_CAND + 4096)                  // 256 float
#define SMEM_DYN (OFF_LOSS + 1024)                  // ~79.4 KB; 2 CTAs/SM ok

__device__ __forceinline__ float tf32_rna(float x) {
    unsigned r; asm("cvt.rna.tf32.f32 %0, %1;" : "=r"(r) : "f"(x));
    return __uint_as_float(r);
}
__device__ __forceinline__ void mma_tf32(float* d, const unsigned* a,
                                         const unsigned* b) {
    asm volatile(
        "mma.sync.aligned.m16n8k8.row.col.f32.tf32.tf32.f32 "
        "{%0,%1,%2,%3}, {%4,%5,%6,%7}, {%8,%9}, {%0,%1,%2,%3};"
        : "+f"(d[0]), "+f"(d[1]), "+f"(d[2]), "+f"(d[3])
        : "r"(a[0]), "r"(a[1]), "r"(a[2]), "r"(a[3]), "r"(b[0]), "r"(b[1]));
}

// ---------------- main kernel ----------------
__global__ void __launch_bounds__(256, 2) vq_mma_kernel(
    const float* __restrict__ z, const float* __restrict__ cb,
    float* __restrict__ out)
{
    extern __shared__ char sm[];
    const int g   = blockIdx.y;
    const int tid = threadIdx.x;
    const int cnt   = g_counts[g];
    const int start = blockIdx.x * TM;
    if (start >= cnt) return;

    float* smA    = (float*)(sm + OFF_A);
    float* smB    = (float*)(sm + OFF_B);
    int*   s_rows = (int*)  (sm + OFF_ROWS);
    float* s_znp  = (float*)(sm + OFF_ZNP);
    float* s_enp  = (float*)(sm + OFF_ENP);
    float* s_zn   = (float*)(sm + OFF_ZN);
    float* s_en   = (float*)(sm + OFF_EN);
    int*   s_sel  = (int*)  (sm + OFF_SEL);
    int*   s_nc   = (int*)  (sm + OFF_NC);
    int*   s_cand = (int*)  (sm + OFF_CAND);
    float* s_loss = (float*)(sm + OFF_LOSS);

    if (tid < TM) {
        int r = (start + tid < cnt) ? g_buckets[g * B_ROWS + start + tid] : -1;
        s_rows[tid] = r;
        s_nc[tid] = 0;
    }
    __syncthreads();

    // loader: thread = 2*row + lh, handles 32 floats of its 64-k chunk half
    const int lrow = tid >> 1, lh = tid & 1;
    const int gr = s_rows[lrow];
    const float* zrow = z  + (size_t)(gr < 0 ? 0 : gr) * D_EMB;
    const float* erow = cb + (size_t)(g * QSIZE + lrow) * D_EMB;

    // mma mapping
    const int w = tid >> 5, lane = tid & 31;
    const int gq = lane >> 2, t = lane & 3;
    const int R0 = w * 16;

    float acc[16][4];
    #pragma unroll
    for (int nf = 0; nf < 16; ++nf)
        #pragma unroll
        for (int q = 0; q < 4; ++q) acc[nf][q] = 0.f;

    float zn_acc = 0.f, en_acc = 0.f;

    #pragma unroll 1
    for (int c = 0; c < 4; ++c) {
        const int kbase = c * 64 + lh * 32;
        float4 zv[8], ev[8];
        #pragma unroll
        for (int j = 0; j < 8; ++j) zv[j] = *(const float4*)(zrow + kbase + 4 * j);
        #pragma unroll
        for (int j = 0; j < 8; ++j) ev[j] = *(const float4*)(erow + kbase + 4 * j);

        __syncthreads();   // previous chunk's mma reads done

        const unsigned aoff = lrow * ROWB + lh * 32;
        #pragma unroll
        for (int j = 0; j < 8; ++j) {
            float4 v = zv[j];
            zn_acc += v.x * v.x; zn_acc += v.y * v.y;
            zn_acc += v.z * v.z; zn_acc += v.w * v.w;
            *(float4*)(smA + aoff + 4 * j) =
                make_float4(tf32_rna(v.x), tf32_rna(v.y),
                            tf32_rna(v.z), tf32_rna(v.w));
            float4 e = ev[j];
            en_acc += e.x * e.x; en_acc += e.y * e.y;
            en_acc += e.z * e.z; en_acc += e.w * e.w;
            *(float4*)(smB + aoff + 4 * j) =
                make_float4(tf32_rna(e.x), tf32_rna(e.y),
                            tf32_rna(e.z), tf32_rna(e.w));
        }
        __syncthreads();

        #pragma unroll
        for (int ks = 0; ks < 8; ++ks) {
            const unsigned abase = (unsigned)(R0 + gq) * ROWB + ks * 8 + t;
            unsigned a[4];
            a[0] = *(const unsigned*)(smA + abase);
            a[1] = *(const unsigned*)(smA + abase + 8 * ROWB);
            a[2] = *(const unsigned*)(smA + abase + 4);
            a[3] = *(const unsigned*)(smA + abase + 8 * ROWB + 4);
            #pragma unroll
            for (int nf = 0; nf < 16; ++nf) {
                const unsigned bbase = (unsigned)(nf * 8 + gq) * ROWB + ks * 8 + t;
                unsigned b[2];
                b[0] = *(const unsigned*)(smB + bbase);
                b[1] = *(const unsigned*)(smB + bbase + 4);
                mma_tf32(acc[nf], a, b);
            }
        }
    }

    s_znp[tid] = zn_acc;
    s_enp[tid] = en_acc;
    __syncthreads();
    if (tid < TM) {
        s_zn[tid] = s_znp[2 * tid] + s_znp[2 * tid + 1];
        s_en[tid] = s_enp[2 * tid] + s_enp[2 * tid + 1];
    }
    __syncthreads();

    // ---- approx argmin per row (two rows per thread) ----
    const int rowA = R0 + gq, rowB = R0 + gq + 8;
    const float znA = s_zn[rowA], znB = s_zn[rowB];
    float vA = CUDART_INF_F, vB = CUDART_INF_F;
    int cA = 0x7fffffff, cB = 0x7fffffff;
    #pragma unroll
    for (int nf = 0; nf < 16; ++nf) {
        #pragma unroll
        for (int q = 0; q < 2; ++q) {
            int col = nf * 8 + 2 * t + q;
            float en = s_en[col];
            float sa = fmaf(-2.f, acc[nf][q],     znA + en);
            float sb = fmaf(-2.f, acc[nf][q + 2], znB + en);
            if (sa < vA || (sa == vA && col < cA)) { vA = sa; cA = col; }
            if (sb < vB || (sb == vB && col < cB)) { vB = sb; cB = col; }
        }
    }
    #pragma unroll
    for (int off = 1; off < 4; off <<= 1) {
        float v2 = __shfl_xor_sync(0xffffffffu, vA, off);
        int   c2 = __shfl_xor_sync(0xffffffffu, cA, off);
        if (v2 < vA || (v2 == vA && c2 < cA)) { vA = v2; cA = c2; }
        v2 = __shfl_xor_sync(0xffffffffu, vB, off);
        c2 = __shfl_xor_sync(0xffffffffu, cB, off);
        if (v2 < vB || (v2 == vB && c2 < cB)) { vB = v2; cB = c2; }
    }
    if (t == 0) { s_sel[rowA] = cA; s_sel[rowB] = cB; }

    // ---- candidate collection within MARGIN of approx min ----
    #pragma unroll
    for (int nf = 0; nf < 16; ++nf) {
        #pragma unroll
        for (int q = 0; q < 2; ++q) {
            int col = nf * 8 + 2 * t + q;
            float en = s_en[col];
            float sa = fmaf(-2.f, acc[nf][q],     znA + en);
            float sb = fmaf(-2.f, acc[nf][q + 2], znB + en);
            if (sa <= vA + MARGIN) {
                int p = atomicAdd(&s_nc[rowA], 1);
                if (p < 8) s_cand[rowA * 8 + p] = col;
            }
            if (sb <= vB + MARGIN) {
                int p = atomicAdd(&s_nc[rowB], 1);
                if (p < 8) s_cand[rowB * 8 + p] = col;
            }
        }
    }
    __syncthreads();

    // ---- exact fp32 rescue for ambiguous rows (warp per row-slice) ----
    for (int m = R0; m < R0 + 16; ++m) {
        int nc = s_nc[m];
        int r  = s_rows[m];
        if (r < 0 || nc <= 1) continue;
        const float* zr = z + (size_t)r * D_EMB;
        float zn = s_zn[m];
        float bestv = CUDART_INF_F;  int bestc = 0x7fffffff;
        int nit = (nc <= 8) ? nc : QSIZE;
        for (int i = 0; i < nit; ++i) {
            int col = (nc <= 8) ? s_cand[m * 8 + i] : i;
            const float* er = cb + (size_t)(g * QSIZE + col) * D_EMB;
            float p = 0.f;
            #pragma unroll
            for (int j = 0; j < 8; ++j)
                p = fmaf(zr[lane + 32 * j], er[lane + 32 * j], p);
            #pragma unroll
            for (int off = 16; off; off >>= 1)
                p += __shfl_xor_sync(0xffffffffu, p, off);
            float sc = fmaf(-2.f, p, zn + s_en[col]);
            if (sc < bestv || (sc == bestv && col < bestc)) { bestv = sc; bestc = col; }
        }
        if (lane == 0) s_sel[m] = bestc;
    }
    __syncthreads();

    if (tid < TM) {
        int r = s_rows[tid];
        if (r >= 0) out[2 + r] = (float)(g * QSIZE + s_sel[tid]);
    }

    // ---- epilogue: st = z + (q - z), per-row loss ----
    {
        int m = tid >> 1, h = tid & 1;
        int r = s_rows[m];
        float lsum = 0.f;
        if (r >= 0) {
            int code = g * QSIZE + s_sel[m];
            const float* zr = z  + (size_t)r    * D_EMB + h * 128;
            const float* qr = cb + (size_t)code * D_EMB + h * 128;
            float* so = out + 2 + B_ROWS + (size_t)r * D_EMB + h * 128;
            #pragma unroll 4
            for (int cc = 0; cc < 128; cc += 4) {
                float4 zv = *(const float4*)(zr + cc);
                float4 qv = *(const float4*)(qr + cc);
                float dx = qv.x - zv.x, dy = qv.y - zv.y;
                float dz = qv.z - zv.z, dw = qv.w - zv.w;
                *(float2*)(so + cc)     = make_float2(zv.x + dx, zv.y + dy);
                *(float2*)(so + cc + 2) = make_float2(zv.z + dz, zv.w + dw);
                lsum += dx * dx; lsum += dy * dy; lsum += dz * dz; lsum += dw * dw;
            }
        }
        s_loss[tid] = lsum;
    }
    __syncthreads();
    if (tid < TM) {
        int r = s_rows[tid];
        if (r >= 0) g_rowloss[r] = s_loss[2 * tid] + s_loss[2 * tid + 1];
    }
}

// ---------------- loss reduction ----------------
__global__ void rowloss_reduce_kernel() {
    __shared__ double sd[256];
    int base = blockIdx.x * 512;
    double s = (double)g_rowloss[base + threadIdx.x]
             + (double)g_rowloss[base + 256 + threadIdx.x];
    sd[threadIdx.x] = s;
    __syncthreads();
    #pragma unroll
    for (int o = 128; o; o >>= 1) {
        if (threadIdx.x < o) sd[threadIdx.x] += sd[threadIdx.x + o];
        __syncthreads();
    }
    if (threadIdx.x == 0) g_bsum[blockIdx.x] = sd[0];
}

__global__ void finalize_kernel(float* __restrict__ out) {
    __shared__ double sd[256];
    sd[threadIdx.x] = g_bsum[threadIdx.x];
    __syncthreads();
    #pragma unroll
    for (int o = 128; o; o >>= 1) {
        if (threadIdx.x < o) sd[threadIdx.x] += sd[threadIdx.x + o];
        __syncthreads();
    }
    if (threadIdx.x == 0) {
        float vq = (float)(sd[0] / ((double)B_ROWS * (double)D_EMB));
        out[0] = vq;
        out[1] = 0.25f * vq;
    }
}

// ---------------- launch ----------------
extern "C" void kernel_launch(void* const* d_in, const int* in_sizes, int n_in,
                              void* d_out, int out_size) {
    const int*   node_type = (const int*)d_in[0];
    const float* z         = (const float*)d_in[1];
    const float* cb        = (const float*)d_in[2];
    float* out = (float*)d_out;

    cudaFuncSetAttribute(vq_mma_kernel,
                         cudaFuncAttributeMaxDynamicSharedMemorySize, SMEM_DYN);

    reset_kernel<<<1, 32>>>();
    classify_kernel<<<B_ROWS / 256, 256>>>(node_type);
    dim3 grid(TILES_M, 4);
    vq_mma_kernel<<<grid, 256, SMEM_DYN>>>(z, cb, out);
    rowloss_reduce_kernel<<<256, 256>>>();
    finalize_kernel<<<1, 256>>>(out);
}

// round 6
// speedup vs baseline: 1.6745x; 1.2106x over previous
#include <cuda_runtime.h>
#include <math_constants.h>

#define B_ROWS   131072
#define D_EMB    256
#define QSIZE    128
#define TM       128
#define TILES_M  (B_ROWS / TM)   // 1024
#define MARGIN   1.0f

// ---------------- device scratch (static) ----------------
__device__ int    g_counts[4];
__device__ int    g_buckets[4 * B_ROWS];
__device__ float  g_rowloss[B_ROWS];
__device__ double g_bsum[256];

// ---------------- small kernels ----------------
__global__ void reset_kernel() {
    if (threadIdx.x < 4) g_counts[threadIdx.x] = 0;
}
// block-aggregated classify: 4 global atomics per block instead of 1/thread
__global__ void classify_kernel(const int* __restrict__ node_type) {
    __shared__ int s_cnt[4];
    __shared__ int s_base[4];
    int tid = threadIdx.x;
    int i = blockIdx.x * blockDim.x + tid;
    if (tid < 4) s_cnt[tid] = 0;
    __syncthreads();
    int t = node_type[i];
    int g = (t == 5) ? 0 : (t == 6) ? 1 : (t == 7) ? 2 : 3;
    int p = atomicAdd(&s_cnt[g], 1);
    __syncthreads();
    if (tid < 4) s_base[tid] = atomicAdd(&g_counts[tid], s_cnt[tid]);
    __syncthreads();
    g_buckets[g * B_ROWS + s_base[g] + p] = i;
}

// ---------------- smem layout ----------------
#define ROWB     68
#define T_FLOATS (128 * ROWB)
#define OFF_A    0
#define OFF_B    (T_FLOATS * 4)
#define OFF_ROWS (2 * T_FLOATS * 4)
#define OFF_ZNP  (OFF_ROWS + 512)
#define OFF_ENP  (OFF_ZNP + 1024)
#define OFF_ZN   (OFF_ENP + 1024)
#define OFF_EN   (OFF_ZN + 512)
#define OFF_SEL  (OFF_EN + 512)
#define OFF_NC   (OFF_SEL + 512)
#define OFF_CAND (OFF_NC + 512)
#define OFF_LOSS (OFF_CAND + 4096)
#define SMEM_DYN (OFF_LOSS + 1024)

__device__ __forceinline__ float tf32_rna(float x) {
    unsigned r; asm("cvt.rna.tf32.f32 %0, %1;" : "=r"(r) : "f"(x));
    return __uint_as_float(r);
}
__device__ __forceinline__ float4 tf32_rna4(float4 v) {
    return make_float4(tf32_rna(v.x), tf32_rna(v.y), tf32_rna(v.z), tf32_rna(v.w));
}
__device__ __forceinline__ void mma_tf32(float* d, const unsigned* a,
                                         const unsigned* b) {
    asm volatile(
        "mma.sync.aligned.m16n8k8.row.col.f32.tf32.tf32.f32 "
        "{%0,%1,%2,%3}, {%4,%5,%6,%7}, {%8,%9}, {%0,%1,%2,%3};"
        : "+f"(d[0]), "+f"(d[1]), "+f"(d[2]), "+f"(d[3])
        : "r"(a[0]), "r"(a[1]), "r"(a[2]), "r"(a[3]), "r"(b[0]), "r"(b[1]));
}

// ---------------- main kernel ----------------
__global__ void __launch_bounds__(256, 2) vq_mma_kernel(
    const float* __restrict__ z, const float* __restrict__ cb,
    float* __restrict__ out)
{
    extern __shared__ char sm[];
    const int g   = blockIdx.y;
    const int tid = threadIdx.x;
    const int cnt   = g_counts[g];
    const int start = blockIdx.x * TM;
    if (start >= cnt) return;

    float* smA    = (float*)(sm + OFF_A);
    float* smB    = (float*)(sm + OFF_B);
    int*   s_rows = (int*)  (sm + OFF_ROWS);
    float* s_znp  = (float*)(sm + OFF_ZNP);
    float* s_enp  = (float*)(sm + OFF_ENP);
    float* s_zn   = (float*)(sm + OFF_ZN);
    float* s_en   = (float*)(sm + OFF_EN);
    int*   s_sel  = (int*)  (sm + OFF_SEL);
    int*   s_nc   = (int*)  (sm + OFF_NC);
    int*   s_cand = (int*)  (sm + OFF_CAND);
    float* s_loss = (float*)(sm + OFF_LOSS);

    if (tid < TM) {
        int r = (start + tid < cnt) ? g_buckets[g * B_ROWS + start + tid] : -1;
        s_rows[tid] = r;
        s_nc[tid] = 0;
    }
    __syncthreads();

    const int lrow = tid >> 1, lh = tid & 1;
    const int gr = s_rows[lrow];
    const float* zrow = z  + (size_t)(gr < 0 ? 0 : gr) * D_EMB;
    const float* erow = cb + (size_t)(g * QSIZE + lrow) * D_EMB;

    const int w = tid >> 5, lane = tid & 31;
    const int gq = lane >> 2, t = lane & 3;
    const int R0 = w * 16;

    float acc[16][4];
    #pragma unroll
    for (int nf = 0; nf < 16; ++nf)
        #pragma unroll
        for (int q = 0; q < 4; ++q) acc[nf][q] = 0.f;

    float zn_acc = 0.f, en_acc = 0.f;

    #pragma unroll 1
    for (int c = 0; c < 4; ++c) {
        const int kbase = c * 64 + lh * 32;
        const unsigned aoff = lrow * ROWB + lh * 32;

        // depth-1 pipelined stream: tiny register footprint, no spills
        float4 vz = *(const float4*)(zrow + kbase);
        float4 ve = *(const float4*)(erow + kbase);

        __syncthreads();   // previous chunk's mma reads done

        #pragma unroll
        for (int j = 0; j < 8; ++j) {
            float4 nz = vz, ne = ve;
            if (j < 7) {
                nz = *(const float4*)(zrow + kbase + 4 * j + 4);
                ne = *(const float4*)(erow + kbase + 4 * j + 4);
            }
            zn_acc += vz.x * vz.x; zn_acc += vz.y * vz.y;
            zn_acc += vz.z * vz.z; zn_acc += vz.w * vz.w;
            en_acc += ve.x * ve.x; en_acc += ve.y * ve.y;
            en_acc += ve.z * ve.z; en_acc += ve.w * ve.w;
            *(float4*)(smA + aoff + 4 * j) = tf32_rna4(vz);
            *(float4*)(smB + aoff + 4 * j) = tf32_rna4(ve);
            vz = nz; ve = ne;
        }
        __syncthreads();

        #pragma unroll
        for (int ks = 0; ks < 8; ++ks) {
            const unsigned abase = (unsigned)(R0 + gq) * ROWB + ks * 8 + t;
            unsigned a[4];
            a[0] = *(const unsigned*)(smA + abase);
            a[1] = *(const unsigned*)(smA + abase + 8 * ROWB);
            a[2] = *(const unsigned*)(smA + abase + 4);
            a[3] = *(const unsigned*)(smA + abase + 8 * ROWB + 4);
            #pragma unroll
            for (int nf = 0; nf < 16; ++nf) {
                const unsigned bbase = (unsigned)(nf * 8 + gq) * ROWB + ks * 8 + t;
                unsigned b[2];
                b[0] = *(const unsigned*)(smB + bbase);
                b[1] = *(const unsigned*)(smB + bbase + 4);
                mma_tf32(acc[nf], a, b);
            }
        }
    }

    s_znp[tid] = zn_acc;
    s_enp[tid] = en_acc;
    __syncthreads();
    if (tid < TM) {
        s_zn[tid] = s_znp[2 * tid] + s_znp[2 * tid + 1];
        s_en[tid] = s_enp[2 * tid] + s_enp[2 * tid + 1];
    }
    __syncthreads();

    // ---- approx argmin per row (two rows per thread) ----
    const int rowA = R0 + gq, rowB = R0 + gq + 8;
    const float znA = s_zn[rowA], znB = s_zn[rowB];
    float vA = CUDART_INF_F, vB = CUDART_INF_F;
    int cA = 0x7fffffff, cB = 0x7fffffff;
    #pragma unroll
    for (int nf = 0; nf < 16; ++nf) {
        #pragma unroll
        for (int q = 0; q < 2; ++q) {
            int col = nf * 8 + 2 * t + q;
            float en = s_en[col];
            float sa = fmaf(-2.f, acc[nf][q],     znA + en);
            float sb = fmaf(-2.f, acc[nf][q + 2], znB + en);
            if (sa < vA || (sa == vA && col < cA)) { vA = sa; cA = col; }
            if (sb < vB || (sb == vB && col < cB)) { vB = sb; cB = col; }
        }
    }
    #pragma unroll
    for (int off = 1; off < 4; off <<= 1) {
        float v2 = __shfl_xor_sync(0xffffffffu, vA, off);
        int   c2 = __shfl_xor_sync(0xffffffffu, cA, off);
        if (v2 < vA || (v2 == vA && c2 < cA)) { vA = v2; cA = c2; }
        v2 = __shfl_xor_sync(0xffffffffu, vB, off);
        c2 = __shfl_xor_sync(0xffffffffu, cB, off);
        if (v2 < vB || (v2 == vB && c2 < cB)) { vB = v2; cB = c2; }
    }
    if (t == 0) { s_sel[rowA] = cA; s_sel[rowB] = cB; }

    // ---- candidate collection within MARGIN of approx min ----
    #pragma unroll
    for (int nf = 0; nf < 16; ++nf) {
        #pragma unroll
        for (int q = 0; q < 2; ++q) {
            int col = nf * 8 + 2 * t + q;
            float en = s_en[col];
            float sa = fmaf(-2.f, acc[nf][q],     znA + en);
            float sb = fmaf(-2.f, acc[nf][q + 2], znB + en);
            if (sa <= vA + MARGIN) {
                int p = atomicAdd(&s_nc[rowA], 1);
                if (p < 8) s_cand[rowA * 8 + p] = col;
            }
            if (sb <= vB + MARGIN) {
                int p = atomicAdd(&s_nc[rowB], 1);
                if (p < 8) s_cand[rowB * 8 + p] = col;
            }
        }
    }
    __syncthreads();

    // ---- exact fp32 rescue for ambiguous rows (warp per row-slice) ----
    for (int m = R0; m < R0 + 16; ++m) {
        int nc = s_nc[m];
        int r  = s_rows[m];
        if (r < 0 || nc <= 1) continue;
        const float* zr = z + (size_t)r * D_EMB;
        float zn = s_zn[m];
        float bestv = CUDART_INF_F;  int bestc = 0x7fffffff;
        int nit = (nc <= 8) ? nc : QSIZE;
        for (int i = 0; i < nit; ++i) {
            int col = (nc <= 8) ? s_cand[m * 8 + i] : i;
            const float* er = cb + (size_t)(g * QSIZE + col) * D_EMB;
            float p = 0.f;
            #pragma unroll
            for (int j = 0; j < 8; ++j)
                p = fmaf(zr[lane + 32 * j], er[lane + 32 * j], p);
            #pragma unroll
            for (int off = 16; off; off >>= 1)
                p += __shfl_xor_sync(0xffffffffu, p, off);
            float sc = fmaf(-2.f, p, zn + s_en[col]);
            if (sc < bestv || (sc == bestv && col < bestc)) { bestv = sc; bestc = col; }
        }
        if (lane == 0) s_sel[m] = bestc;
    }
    __syncthreads();

    if (tid < TM) {
        int r = s_rows[tid];
        if (r >= 0) out[2 + r] = (float)(g * QSIZE + s_sel[tid]);
    }

    // ---- epilogue: st = z + (q - z), per-row loss ----
    {
        int m = tid >> 1, h = tid & 1;
        int r = s_rows[m];
        float lsum = 0.f;
        if (r >= 0) {
            int code = g * QSIZE + s_sel[m];
            const float* zr = z  + (size_t)r    * D_EMB + h * 128;
            const float* qr = cb + (size_t)code * D_EMB + h * 128;
            float* so = out + 2 + B_ROWS + (size_t)r * D_EMB + h * 128;
            #pragma unroll 4
            for (int cc = 0; cc < 128; cc += 4) {
                float4 zv = *(const float4*)(zr + cc);
                float4 qv = *(const float4*)(qr + cc);
                float dx = qv.x - zv.x, dy = qv.y - zv.y;
                float dz = qv.z - zv.z, dw = qv.w - zv.w;
                *(float2*)(so + cc)     = make_float2(zv.x + dx, zv.y + dy);
                *(float2*)(so + cc + 2) = make_float2(zv.z + dz, zv.w + dw);
                lsum += dx * dx; lsum += dy * dy; lsum += dz * dz; lsum += dw * dw;
            }
        }
        s_loss[tid] = lsum;
    }
    __syncthreads();
    if (tid < TM) {
        int r = s_rows[tid];
        if (r >= 0) g_rowloss[r] = s_loss[2 * tid] + s_loss[2 * tid + 1];
    }
}

// ---------------- loss reduction ----------------
__global__ void rowloss_reduce_kernel() {
    __shared__ double sd[256];
    int base = blockIdx.x * 512;
    double s = (double)g_rowloss[base + threadIdx.x]
             + (double)g_rowloss[base + 256 + threadIdx.x];
    sd[threadIdx.x] = s;
    __syncthreads();
    #pragma unroll
    for (int o = 128; o; o >>= 1) {
        if (threadIdx.x < o) sd[threadIdx.x] += sd[threadIdx.x + o];
        __syncthreads();
    }
    if (threadIdx.x == 0) g_bsum[blockIdx.x] = sd[0];
}

__global__ void finalize_kernel(float* __restrict__ out) {
    __shared__ double sd[256];
    sd[threadIdx.x] = g_bsum[threadIdx.x];
    __syncthreads();
    #pragma unroll
    for (int o = 128; o; o >>= 1) {
        if (threadIdx.x < o) sd[threadIdx.x] += sd[threadIdx.x + o];
        __syncthreads();
    }
    if (threadIdx.x == 0) {
        float vq = (float)(sd[0] / ((double)B_ROWS * (double)D_EMB));
        out[0] = vq;
        out[1] = 0.25f * vq;
    }
}

// ---------------- launch ----------------
extern "C" void kernel_launch(void* const* d_in, const int* in_sizes, int n_in,
                              void* d_out, int out_size) {
    const int*   node_type = (const int*)d_in[0];
    const float* z         = (const float*)d_in[1];
    const float* cb        = (const float*)d_in[2];
    float* out = (float*)d_out;

    cudaFuncSetAttribute(vq_mma_kernel,
                         cudaFuncAttributeMaxDynamicSharedMemorySize, SMEM_DYN);

    reset_kernel<<<1, 32>>>();
    classify_kernel<<<B_ROWS / 256, 256>>>(node_type);
    dim3 grid(TILES_M, 4);
    vq_mma_kernel<<<grid, 256, SMEM_DYN>>>(z, cb, out);
    rowloss_reduce_kernel<<<256, 256>>>();
    finalize_kernel<<<1, 256>>>(out);
}